// round 15
// baseline (speedup 1.0000x reference)
#include <cuda_runtime.h>
#include <cuda_bf16.h>
#include <cstdint>

#define R_TOTAL 32768   // 16384 b * 2 (values,mask)
#define NE      1024
#define H       128
#define NCH     32      // K-chunks of 32
#define NTILES  256     // 128-row M-tiles
#define NCHUNKS 4096    // 4-batch head chunks

// Scratch: vm[2b+0]=values row, vm[2b+1]=mask row.
__device__ float g_vm[(size_t)R_TOTAL * H];
__device__ int g_flag[NTILES];
__device__ unsigned int g_ticket;

// W pre-split into bf16 hi/lo, paired m16n8k16 B-fragment order.
__device__ uint32_t g_Bh[64 * 8 * 32 * 4];
__device__ uint32_t g_Bl[64 * 8 * 32 * 4];

// ---------------------------------------------------------------------------
// Kernel 0: split W -> fragments; also reset flags/ticket for this launch.
// ---------------------------------------------------------------------------
__global__ void prep_w(const float* __restrict__ W) {
    if (threadIdx.x == 0) g_flag[blockIdx.x] = 0;
    if (blockIdx.x == 0 && threadIdx.x == 1) g_ticket = 0;

    int idx = blockIdx.x * 256 + threadIdx.x;
    if (idx >= H * (NE / 2)) return;
    int h  = idx >> 9;
    int kp = idx & 511;
    int k  = kp * 2;

    float w0 = W[(size_t)h * NE + k];
    float w1 = W[(size_t)h * NE + k + 1];
    uint32_t b0 = __float_as_uint(w0), b1 = __float_as_uint(w1);
    uint32_t hi;
    asm("prmt.b32 %0, %1, %2, 0x7632;" : "=r"(hi) : "r"(b0), "r"(b1));
    float l0 = w0 - __uint_as_float(b0 & 0xFFFF0000u);
    float l1 = w1 - __uint_as_float(b1 & 0xFFFF0000u);
    uint32_t lo;
    asm("cvt.rn.bf16x2.f32 %0, %1, %2;" : "=r"(lo) : "f"(l1), "f"(l0));

    int kstep = kp >> 3;
    int natom = h >> 3;
    int pair  = natom >> 1;
    int q     = natom & 1;
    int lane  = 4 * (h & 7) + (kp & 3);
    int reg   = (kp >> 2) & 1;
    int out   = ((kstep * 8 + pair) * 32 + lane) * 4 + q * 2 + reg;
    g_Bh[out] = hi;
    g_Bl[out] = lo;
}

// ---------------------------------------------------------------------------
__device__ __forceinline__ void mma_bf16(float* d, const uint32_t* a,
                                         uint32_t b0, uint32_t b1) {
    asm volatile(
        "mma.sync.aligned.m16n8k16.row.col.f32.bf16.bf16.f32 "
        "{%0,%1,%2,%3}, {%4,%5,%6,%7}, {%8,%9}, {%0,%1,%2,%3};"
        : "+f"(d[0]), "+f"(d[1]), "+f"(d[2]), "+f"(d[3])
        : "r"(a[0]), "r"(a[1]), "r"(a[2]), "r"(a[3]), "r"(b0), "r"(b1));
}
__device__ __forceinline__ uint32_t smem_u32(const void* p) {
    uint32_t a;
    asm("{ .reg .u64 t; cvta.to.shared.u64 t, %1; cvt.u32.u64 %0, t; }"
        : "=r"(a) : "l"(p));
    return a;
}
__device__ __forceinline__ void cp_async16(uint32_t s, const void* g) {
    asm volatile("cp.async.cg.shared.global [%0], [%1], 16;"
                 :: "r"(s), "l"(g) : "memory");
}
__device__ __forceinline__ float ex2f(float x) {
    float r;
    asm("ex2.approx.ftz.f32 %0, %1;" : "=f"(r) : "f"(x));
    return r;
}
// Reciprocal on the FMA pipe: bit-trick seed + 2 Newton steps.
__device__ __forceinline__ float nrcp(float s) {
    float y = __uint_as_float(0x7EF311C3u - __float_as_uint(s));
    y = y * fmaf(-s, y, 2.0f);
    y = y * fmaf(-s, y, 2.0f);
    return y;
}
#define BAR0() asm volatile("bar.sync 0, 256;" ::: "memory")

// ---------------------------------------------------------------------------
// Warp-autonomous head: 4 batches (2 pairs), validated R8/R9 math.
// ---------------------------------------------------------------------------
__device__ void warp_head4(int b0, const float* __restrict__ cov,
                           float4 blf, float* __restrict__ out, int lane) {
    #pragma unroll 1
    for (int p = 0; p < 2; ++p) {
        const int ba = b0 + 2 * p;
        const int bb = ba + 1;
        float v0[4], m0[4], v1[4], m1[4];
        #pragma unroll
        for (int r = 0; r < 4; ++r) {
            v0[r] = g_vm[(size_t)(2 * ba + 0) * H + r * 32 + lane];
            m0[r] = g_vm[(size_t)(2 * ba + 1) * H + r * 32 + lane]
                    * 1.4426950408889634f;
            v1[r] = g_vm[(size_t)(2 * bb + 0) * H + r * 32 + lane];
            m1[r] = g_vm[(size_t)(2 * bb + 1) * H + r * 32 + lane]
                    * 1.4426950408889634f;
        }
        float a00 = 0.f, a01 = 0.f, a02 = 0.f, a03 = 0.f;
        float a10 = 0.f, a11 = 0.f, a12 = 0.f, a13 = 0.f;
        #pragma unroll
        for (int hc = 0; hc < 4; ++hc) {
            #pragma unroll 8
            for (int i = 0; i < 32; ++i) {
                const int h = hc * 32 + i;
                const float mh0 = __shfl_sync(0xffffffffu, m0[hc], i);
                const float mh1 = __shfl_sync(0xffffffffu, m1[hc], i);
                const float4 c = __ldg(reinterpret_cast<const float4*>(
                                           cov + (size_t)h * H) + lane);
                const float e00 = ex2f(mh0 * c.x), e01 = ex2f(mh0 * c.y);
                const float e02 = ex2f(mh0 * c.z), e03 = ex2f(mh0 * c.w);
                const float e10 = ex2f(mh1 * c.x), e11 = ex2f(mh1 * c.y);
                const float e12 = ex2f(mh1 * c.z), e13 = ex2f(mh1 * c.w);
                float s0 = (e00 + e01) + (e02 + e03);
                float s1 = (e10 + e11) + (e12 + e13);
                #pragma unroll
                for (int d = 16; d > 0; d >>= 1) {
                    s0 += __shfl_xor_sync(0xffffffffu, s0, d);
                    s1 += __shfl_xor_sync(0xffffffffu, s1, d);
                }
                const float vh0 = __shfl_sync(0xffffffffu, v0[hc], i);
                const float vh1 = __shfl_sync(0xffffffffu, v1[hc], i);
                const float w0 = vh0 * nrcp(s0);
                const float w1 = vh1 * nrcp(s1);
                a00 = fmaf(w0, e00, a00); a01 = fmaf(w0, e01, a01);
                a02 = fmaf(w0, e02, a02); a03 = fmaf(w0, e03, a03);
                a10 = fmaf(w1, e10, a10); a11 = fmaf(w1, e11, a11);
                a12 = fmaf(w1, e12, a12); a13 = fmaf(w1, e13, a13);
            }
        }
        *reinterpret_cast<float4*>(&out[(size_t)ba * H + 4 * lane]) =
            make_float4(a00 + blf.x, a01 + blf.y, a02 + blf.z, a03 + blf.w);
        *reinterpret_cast<float4*>(&out[(size_t)bb * H + 4 * lane]) =
            make_float4(a10 + blf.x, a11 + blf.y, a12 + blf.z, a13 + blf.w);
    }
}

// ---------------------------------------------------------------------------
// Fused persistent kernel, grid 148 x 384 (1 CTA/SM):
//   threads 0-255 (8 warps): gemm tiles (grid-stride), then join consumers.
//   threads 256-383 (4 warps): head consumers from the start.
// ---------------------------------------------------------------------------
__global__ __launch_bounds__(384, 1) void fused(const float* __restrict__ X,
                                                const float* __restrict__ cov,
                                                const float* __restrict__ bias,
                                                float* __restrict__ out) {
    __shared__ uint32_t sA[4096];       // 16KB: hi[2048] | lo[2048]
    __shared__ uint32_t sB[2][4096];    // 32KB
    uint32_t* sAh = sA;
    uint32_t* sAl = sA + 2048;

    const int tid  = threadIdx.x;
    const int lane = tid & 31;
    const float4 blf = __ldg(reinterpret_cast<const float4*>(bias) + lane);

    if (tid < 256) {
        // ================= gemm role (8 warps, 256 threads) =================
        const int wid = tid >> 5;
        const int wm  = wid & 3;
        const int wn  = wid >> 2;
        const int ar[4] = { (tid + 0)   >> 3, (tid + 256) >> 3,
                            (tid + 512) >> 3, (tid + 768) >> 3 };
        const int ac4   = tid & 7;

        for (int t = blockIdx.x; t < NTILES; t += gridDim.x) {
            const int row0 = t * 128;

            float acc[2][8][4];
            #pragma unroll
            for (int i = 0; i < 2; ++i)
                #pragma unroll
                for (int j = 0; j < 8; ++j)
                    #pragma unroll
                    for (int q = 0; q < 4; ++q) acc[i][j][q] = 0.f;

            float4 pref[4];
            #pragma unroll
            for (int j = 0; j < 4; ++j)
                pref[j] = __ldg(reinterpret_cast<const float4*>(
                                    X + (size_t)(row0 + ar[j]) * NE) + ac4);
            {
                const char* gh = reinterpret_cast<const char*>(g_Bh);
                const char* gl = reinterpret_cast<const char*>(g_Bl);
                uint32_t db = smem_u32(sB[0]);
                int e = tid * 16;
                cp_async16(db + e,               gh + e);
                cp_async16(db + 8192 + e,        gl + e);
                cp_async16(db + e + 4096,        gh + e + 4096);
                cp_async16(db + 8192 + e + 4096, gl + e + 4096);
                asm volatile("cp.async.commit_group;" ::: "memory");
            }

            for (int c = 0; c < NCH; ++c) {
                const int cur = c & 1;
                BAR0();   // prior MMA reads of sA / sB[cur^1] retired

                #pragma unroll
                for (int j = 0; j < 4; ++j) {
                    float4 v = pref[j];
                    uint32_t x0 = __float_as_uint(v.x), x1 = __float_as_uint(v.y);
                    uint32_t x2 = __float_as_uint(v.z), x3 = __float_as_uint(v.w);
                    uint32_t hi01, hi23;
                    asm("prmt.b32 %0, %1, %2, 0x7632;" : "=r"(hi01) : "r"(x0), "r"(x1));
                    asm("prmt.b32 %0, %1, %2, 0x7632;" : "=r"(hi23) : "r"(x2), "r"(x3));
                    float l0 = v.x - __uint_as_float(x0 & 0xFFFF0000u);
                    float l1 = v.y - __uint_as_float(x1 & 0xFFFF0000u);
                    float l2 = v.z - __uint_as_float(x2 & 0xFFFF0000u);
                    float l3 = v.w - __uint_as_float(x3 & 0xFFFF0000u);
                    uint32_t lo01, lo23;
                    asm("cvt.rn.bf16x2.f32 %0, %1, %2;" : "=r"(lo01) : "f"(l1), "f"(l0));
                    asm("cvt.rn.bf16x2.f32 %0, %1, %2;" : "=r"(lo23) : "f"(l3), "f"(l2));
                    int rr = ar[j] & 15, a = ar[j] >> 4;
                    #pragma unroll
                    for (int p = 0; p < 2; ++p) {
                        int cc = 2 * ac4 + p;
                        int s  = cc >> 3;
                        int c8 = cc & 7;
                        int ln = (rr & 7) * 4 + (c8 & 3);
                        int rg = (rr >> 3) + 2 * (c8 >> 2);
                        int e  = ((s * 8 + a) * 32 + ln) * 4 + rg;
                        sAh[e] = p ? hi23 : hi01;
                        sAl[e] = p ? lo23 : lo01;
                    }
                }

                if (c + 1 < NCH) {
                    const char* gh = reinterpret_cast<const char*>(g_Bh + (c + 1) * 2048);
                    const char* gl = reinterpret_cast<const char*>(g_Bl + (c + 1) * 2048);
                    uint32_t db = smem_u32(sB[cur ^ 1]);
                    int e = tid * 16;
                    cp_async16(db + e,               gh + e);
                    cp_async16(db + 8192 + e,        gl + e);
                    cp_async16(db + e + 4096,        gh + e + 4096);
                    cp_async16(db + 8192 + e + 4096, gl + e + 4096);
                    asm volatile("cp.async.commit_group;" ::: "memory");
                    const float* Xn = X + (c + 1) * 32;
                    #pragma unroll
                    for (int j = 0; j < 4; ++j)
                        pref[j] = __ldg(reinterpret_cast<const float4*>(
                                            Xn + (size_t)(row0 + ar[j]) * NE) + ac4);
                    asm volatile("cp.async.wait_group 1;" ::: "memory");
                } else {
                    asm volatile("cp.async.wait_group 0;" ::: "memory");
                }
                BAR0();   // sA converted + sB[cur] landed

                uint32_t* Bh = sB[cur];
                uint32_t* Bl = sB[cur] + 2048;

                #pragma unroll
                for (int s = 0; s < 2; ++s) {
                    uint32_t ah[2][4], al[2][4];
                    #pragma unroll
                    for (int i = 0; i < 2; ++i) {
                        const uint32_t* pa = &sAh[((s * 8 + wm * 2 + i) * 32 + lane) * 4];
                        ah[i][0] = pa[0]; ah[i][1] = pa[1]; ah[i][2] = pa[2]; ah[i][3] = pa[3];
                        const uint32_t* pl = &sAl[((s * 8 + wm * 2 + i) * 32 + lane) * 4];
                        al[i][0] = pl[0]; al[i][1] = pl[1]; al[i][2] = pl[2]; al[i][3] = pl[3];
                    }
                    #pragma unroll
                    for (int jh = 0; jh < 2; ++jh) {
                        uint4 bhp[2], blp[2];
                        #pragma unroll
                        for (int jp = 0; jp < 2; ++jp) {
                            int pi = wn * 4 + jh * 2 + jp;
                            bhp[jp] = *reinterpret_cast<const uint4*>(
                                &Bh[((s * 8 + pi) * 32 + lane) * 4]);
                            blp[jp] = *reinterpret_cast<const uint4*>(
                                &Bl[((s * 8 + pi) * 32 + lane) * 4]);
                        }
                        const uint32_t bh[4][2] = {
                            {bhp[0].x, bhp[0].y}, {bhp[0].z, bhp[0].w},
                            {bhp[1].x, bhp[1].y}, {bhp[1].z, bhp[1].w}};
                        const uint32_t bl[4][2] = {
                            {blp[0].x, blp[0].y}, {blp[0].z, blp[0].w},
                            {blp[1].x, blp[1].y}, {blp[1].z, blp[1].w}};
                        #pragma unroll
                        for (int i = 0; i < 2; ++i)
                            #pragma unroll
                            for (int jj = 0; jj < 4; ++jj) {
                                float* d = acc[i][jh * 4 + jj];
                                mma_bf16(d, ah[i], bh[jj][0], bh[jj][1]);
                                mma_bf16(d, ah[i], bl[jj][0], bl[jj][1]);
                                mma_bf16(d, al[i], bh[jj][0], bh[jj][1]);
                            }
                    }
                }
            }

            // epilogue -> g_vm, then publish flag
            #pragma unroll
            for (int i = 0; i < 2; ++i) {
                int grow = row0 + wm * 32 + i * 16 + (lane >> 2);
                #pragma unroll
                for (int j = 0; j < 8; ++j) {
                    int gcol = wn * 64 + j * 8 + 2 * (lane & 3);
                    float2* p0 = reinterpret_cast<float2*>(&g_vm[(size_t)grow * H + gcol]);
                    float2* p1 = reinterpret_cast<float2*>(&g_vm[(size_t)(grow + 8) * H + gcol]);
                    *p0 = make_float2(acc[i][j][0], acc[i][j][1]);
                    *p1 = make_float2(acc[i][j][2], acc[i][j][3]);
                }
            }
            __threadfence();
            BAR0();   // all epilogue stores fenced; also retires MMA reads
            if (tid == 0) atomicExch(&g_flag[t], 1);
        }
    }

    // ================= consumer role (all warps end up here) =================
    while (true) {
        unsigned int c;
        if (lane == 0) c = atomicAdd(&g_ticket, 1u);
        c = __shfl_sync(0xffffffffu, c, 0);
        if (c >= NCHUNKS) break;
        const int tile = (int)(c >> 4);
        if (lane == 0) {
            while (atomicAdd(&g_flag[tile], 0) == 0) __nanosleep(64);
        }
        __syncwarp();
        __threadfence();   // acquire: order g_vm reads after flag observation
        warp_head4((int)c * 4, cov, blf, out, lane);
    }
}

// ---------------------------------------------------------------------------
extern "C" void kernel_launch(void* const* d_in, const int* in_sizes, int n_in,
                              void* d_out, int out_size) {
    const float* x    = (const float*)d_in[0];  // [16384,2,1024]
    const float* W    = (const float*)d_in[1];  // [128,1024]
    const float* cov  = (const float*)d_in[2];  // [128,128]
    const float* bias = (const float*)d_in[3];  // [128]
    float*       out  = (float*)d_out;          // [16384,128]

    prep_w<<<(H * NE / 2 + 255) / 256, 256>>>(W);
    fused<<<148, 384>>>(x, cov, bias, out);
}